// round 1
// baseline (speedup 1.0000x reference)
#include <cuda_runtime.h>
#include <cstdint>

// Grouped GEMM: C[M,N], A[M,K] fp32, B[E,N,K] fp32 (column-major weights -> dot over K).
// Segments are contiguous row ranges given by seg_indptr[E+1]; expert per segment via weight_indices.
// Round-1 strategy: SIMT fp32 GEMM with packed fma.rn.f32x2 (FFMA2) accumulators.

#define BM 128
#define BN 128
#define BK 16
#define THREADS 256

constexpr int K_DIM = 1024;
constexpr int N_DIM = 1024;
constexpr int E_SEG = 8;
constexpr int KT = K_DIM / BK;       // 64 k-tiles
constexpr int AS_S = BM + 4;         // padded smem stride (floats)
constexpr int BS_S = BN + 4;

__device__ __forceinline__ unsigned long long pack2(float x, float y) {
    unsigned long long r;
    asm("mov.b64 %0, {%1, %2};"
        : "=l"(r) : "r"(__float_as_uint(x)), "r"(__float_as_uint(y)));
    return r;
}

__device__ __forceinline__ float2 unpack2(unsigned long long v) {
    unsigned int a, b;
    asm("mov.b64 {%0, %1}, %2;" : "=r"(a), "=r"(b) : "l"(v));
    return make_float2(__uint_as_float(a), __uint_as_float(b));
}

// Packed dual-FMA: d.lo += a.lo*b.lo; d.hi += a.hi*b.hi  (Blackwell f32x2 pipe)
__device__ __forceinline__ void fma2(unsigned long long& d,
                                     unsigned long long a,
                                     unsigned long long b) {
    asm("fma.rn.f32x2 %0, %1, %2, %0;" : "+l"(d) : "l"(a), "l"(b));
}

__global__ void __launch_bounds__(THREADS)
grouped_gemm_f32x2(const float* __restrict__ A,
                   const float* __restrict__ B,
                   const int* __restrict__ seg_indptr,
                   const int* __restrict__ widx,
                   float* __restrict__ C)
{
    __shared__ float As[2][BK][AS_S];   // transposed: As[k][m]
    __shared__ float Bs[2][BK][BS_S];   // transposed: Bs[k][n]

    const int tid  = threadIdx.x;
    const int row0 = blockIdx.y * BM;
    const int col0 = blockIdx.x * BN;

    const int ty = tid >> 4;            // 0..15 -> output rows ty*8..ty*8+7
    const int tx = tid & 15;            // 0..15 -> output cols tx*8..tx*8+7

    // Tile-load mapping: each thread stages 2x float4 of A and 2x float4 of B.
    const int lr = tid >> 2;            // 0..63 (tile row; second chunk at +64)
    const int lk = (tid & 3) << 2;      // k offset within tile: 0,4,8,12

    #pragma unroll 1
    for (int s = 0; s < E_SEG; ++s) {
        const int slo = seg_indptr[s];
        const int shi = seg_indptr[s + 1];
        const int rlo = max(slo, row0);
        const int rhi = min(shi, row0 + BM);
        if (rlo >= rhi) continue;       // segment doesn't intersect this row band

        const float* __restrict__ Bw = B + (size_t)widx[s] * ((size_t)N_DIM * K_DIM);

        unsigned long long acc[8][4];
        #pragma unroll
        for (int i = 0; i < 8; ++i)
            #pragma unroll
            for (int j = 0; j < 4; ++j) acc[i][j] = 0ull;

        const float* Aptr = A  + (size_t)(row0 + lr) * K_DIM + lk;
        const float* Bptr = Bw + (size_t)(col0 + lr) * K_DIM + lk;

        // Prologue: stage k-tile 0 into registers.
        float4 pa0 = *(const float4*)(Aptr);
        float4 pa1 = *(const float4*)(Aptr + (size_t)64 * K_DIM);
        float4 pb0 = *(const float4*)(Bptr);
        float4 pb1 = *(const float4*)(Bptr + (size_t)64 * K_DIM);

        #pragma unroll 1
        for (int kt = 0; kt < KT; ++kt) {
            const int buf = kt & 1;

            // Store staged tile (transposed) into smem.
            As[buf][lk + 0][lr]      = pa0.x;
            As[buf][lk + 1][lr]      = pa0.y;
            As[buf][lk + 2][lr]      = pa0.z;
            As[buf][lk + 3][lr]      = pa0.w;
            As[buf][lk + 0][lr + 64] = pa1.x;
            As[buf][lk + 1][lr + 64] = pa1.y;
            As[buf][lk + 2][lr + 64] = pa1.z;
            As[buf][lk + 3][lr + 64] = pa1.w;

            Bs[buf][lk + 0][lr]      = pb0.x;
            Bs[buf][lk + 1][lr]      = pb0.y;
            Bs[buf][lk + 2][lr]      = pb0.z;
            Bs[buf][lk + 3][lr]      = pb0.w;
            Bs[buf][lk + 0][lr + 64] = pb1.x;
            Bs[buf][lk + 1][lr + 64] = pb1.y;
            Bs[buf][lk + 2][lr + 64] = pb1.z;
            Bs[buf][lk + 3][lr + 64] = pb1.w;

            __syncthreads();

            // Prefetch next k-tile into registers (overlaps with compute below).
            if (kt + 1 < KT) {
                const float* An = Aptr + (size_t)(kt + 1) * BK;
                const float* Bn = Bptr + (size_t)(kt + 1) * BK;
                pa0 = *(const float4*)(An);
                pa1 = *(const float4*)(An + (size_t)64 * K_DIM);
                pb0 = *(const float4*)(Bn);
                pb1 = *(const float4*)(Bn + (size_t)64 * K_DIM);
            }

            // Compute 16 k-steps on the current buffer.
            #pragma unroll
            for (int kk = 0; kk < BK; ++kk) {
                const float4 av0 = *(const float4*)&As[buf][kk][ty * 8];
                const float4 av1 = *(const float4*)&As[buf][kk][ty * 8 + 4];
                const float4 bv0 = *(const float4*)&Bs[buf][kk][tx * 8];
                const float4 bv1 = *(const float4*)&Bs[buf][kk][tx * 8 + 4];

                const unsigned long long b01 = pack2(bv0.x, bv0.y);
                const unsigned long long b23 = pack2(bv0.z, bv0.w);
                const unsigned long long b45 = pack2(bv1.x, bv1.y);
                const unsigned long long b67 = pack2(bv1.z, bv1.w);

                const float a[8] = {av0.x, av0.y, av0.z, av0.w,
                                    av1.x, av1.y, av1.z, av1.w};
                #pragma unroll
                for (int i = 0; i < 8; ++i) {
                    const unsigned long long ap = pack2(a[i], a[i]);
                    fma2(acc[i][0], ap, b01);
                    fma2(acc[i][1], ap, b23);
                    fma2(acc[i][2], ap, b45);
                    fma2(acc[i][3], ap, b67);
                }
            }
            __syncthreads();
        }

        // Epilogue: write only rows inside this segment's intersection.
        #pragma unroll
        for (int i = 0; i < 8; ++i) {
            const int r = row0 + ty * 8 + i;
            if (r >= rlo && r < rhi) {
                const float2 v0 = unpack2(acc[i][0]);
                const float2 v1 = unpack2(acc[i][1]);
                const float2 v2 = unpack2(acc[i][2]);
                const float2 v3 = unpack2(acc[i][3]);
                float* __restrict__ out = &C[(size_t)r * N_DIM + col0 + tx * 8];
                *(float4*)(out)     = make_float4(v0.x, v0.y, v1.x, v1.y);
                *(float4*)(out + 4) = make_float4(v2.x, v2.y, v3.x, v3.y);
            }
        }
    }
}

extern "C" void kernel_launch(void* const* d_in, const int* in_sizes, int n_in,
                              void* d_out, int out_size)
{
    const float* a = (const float*)d_in[0];               // [M, K]
    const float* b = (const float*)d_in[1];               // [E, N, K]
    // Locate int inputs robustly by element count: seg_indptr has E+1=9, weight_indices has E=8.
    const int* seg  = nullptr;
    const int* widx = nullptr;
    for (int i = 0; i < n_in; ++i) {
        if (in_sizes[i] == E_SEG + 1)      seg  = (const int*)d_in[i];
        else if (in_sizes[i] == E_SEG)     widx = (const int*)d_in[i];
    }
    float* c = (float*)d_out;

    const int Mtot = in_sizes[0] / K_DIM;                  // 8192
    dim3 grid(N_DIM / BN, Mtot / BM);                      // (8, 64) = 512 CTAs
    grouped_gemm_f32x2<<<grid, THREADS>>>(a, b, seg, widx, c);
}

// round 3
// speedup vs baseline: 2.0258x; 2.0258x over previous
#include <cuda_runtime.h>
#include <cuda_bf16.h>
#include <cstdint>

// Grouped GEMM via bf16 3-term split on mma.sync (HMMA, base sm_103 target).
// C[M,N] = A[M,K] @ B[e,N,K]^T per contiguous row segment.

constexpr int M_DIM = 8192;
constexpr int K_DIM = 1024;
constexpr int N_DIM = 1024;
constexpr int E_SEG = 8;

#define BM 128
#define BN 128
#define BK 32
#define THREADS 256
constexpr int KT = K_DIM / BK;          // 32 k-chunks
constexpr int PITCH = 80;               // smem row pitch in bytes (40 bf16)
constexpr int MAT_BYTES = 128 * PITCH;  // 10240 per matrix tile
constexpr int STAGE_BYTES = 4 * MAT_BYTES;  // Ahi,Alo,Bhi,Blo = 40960
constexpr int NSTAGE = 4;
constexpr int SMEM_TOTAL = NSTAGE * STAGE_BYTES;  // 163840

// Split storage (bf16)
__device__ __nv_bfloat16 g_Ahi[(size_t)M_DIM * K_DIM];
__device__ __nv_bfloat16 g_Alo[(size_t)M_DIM * K_DIM];
__device__ __nv_bfloat16 g_Bhi[(size_t)E_SEG * N_DIM * K_DIM];
__device__ __nv_bfloat16 g_Blo[(size_t)E_SEG * N_DIM * K_DIM];

// ---------------- split prepass ----------------
__device__ __forceinline__ void split4(float4 v, ushort4& h, ushort4& l) {
    __nv_bfloat16 h0 = __float2bfloat16(v.x), h1 = __float2bfloat16(v.y);
    __nv_bfloat16 h2 = __float2bfloat16(v.z), h3 = __float2bfloat16(v.w);
    __nv_bfloat16 l0 = __float2bfloat16(v.x - __bfloat162float(h0));
    __nv_bfloat16 l1 = __float2bfloat16(v.y - __bfloat162float(h1));
    __nv_bfloat16 l2 = __float2bfloat16(v.z - __bfloat162float(h2));
    __nv_bfloat16 l3 = __float2bfloat16(v.w - __bfloat162float(h3));
    h = make_ushort4(__bfloat16_as_ushort(h0), __bfloat16_as_ushort(h1),
                     __bfloat16_as_ushort(h2), __bfloat16_as_ushort(h3));
    l = make_ushort4(__bfloat16_as_ushort(l0), __bfloat16_as_ushort(l1),
                     __bfloat16_as_ushort(l2), __bfloat16_as_ushort(l3));
}
__global__ void __launch_bounds__(256) split_A(const float4* __restrict__ src) {
    size_t i = (size_t)blockIdx.x * 256 + threadIdx.x;
    ushort4 h, l; split4(src[i], h, l);
    ((ushort4*)g_Ahi)[i] = h; ((ushort4*)g_Alo)[i] = l;
}
__global__ void __launch_bounds__(256) split_B(const float4* __restrict__ src) {
    size_t i = (size_t)blockIdx.x * 256 + threadIdx.x;
    ushort4 h, l; split4(src[i], h, l);
    ((ushort4*)g_Bhi)[i] = h; ((ushort4*)g_Blo)[i] = l;
}

// ---------------- asm helpers ----------------
__device__ __forceinline__ void cp16(uint32_t dst, const void* src) {
    asm volatile("cp.async.cg.shared.global [%0], [%1], 16;" :: "r"(dst), "l"(src));
}
__device__ __forceinline__ void ldsm4(uint32_t addr, uint32_t r[4]) {
    asm volatile("ldmatrix.sync.aligned.m8n8.x4.shared.b16 {%0,%1,%2,%3}, [%4];"
                 : "=r"(r[0]), "=r"(r[1]), "=r"(r[2]), "=r"(r[3]) : "r"(addr));
}
__device__ __forceinline__ void mma16816(float d[4], const uint32_t a[4],
                                         uint32_t b0, uint32_t b1) {
    asm volatile(
        "mma.sync.aligned.m16n8k16.row.col.f32.bf16.bf16.f32 "
        "{%0,%1,%2,%3}, {%4,%5,%6,%7}, {%8,%9}, {%0,%1,%2,%3};"
        : "+f"(d[0]), "+f"(d[1]), "+f"(d[2]), "+f"(d[3])
        : "r"(a[0]), "r"(a[1]), "r"(a[2]), "r"(a[3]), "r"(b0), "r"(b1));
}

// ---------------- main kernel ----------------
__global__ void __launch_bounds__(THREADS, 1)
grouped_gemm_hmma(const int* __restrict__ seg_indptr,
                  const int* __restrict__ widx,
                  float* __restrict__ C)
{
    extern __shared__ char smem[];
    const uint32_t sb = (uint32_t)__cvta_generic_to_shared(smem);
    const int tid = threadIdx.x;
    const int wid = tid >> 5;
    const int lane = tid & 31;
    const int warp_m = wid >> 2;           // 0..1 -> row offset *64
    const int warp_n = wid & 3;            // 0..3 -> col offset *32
    const int row0 = blockIdx.y * BM;
    const int col0 = blockIdx.x * BN;

    // ldmatrix lane addressing components
    const int aRow  = warp_m * 64 + (lane & 15);
    const int aColB = (lane >> 4) * 16;
    const int bRow  = warp_n * 32 + (lane & 7) + ((lane >> 4) & 1) * 8;
    const int bColB = ((lane >> 3) & 1) * 16;

    #pragma unroll 1
    for (int s = 0; s < E_SEG; ++s) {
        const int slo = seg_indptr[s];
        const int shi = seg_indptr[s + 1];
        const int rlo = max(slo, row0);
        const int rhi = min(shi, row0 + BM);
        if (rlo >= rhi) continue;

        const size_t wbase = (size_t)widx[s] * ((size_t)N_DIM * K_DIM);
        const __nv_bfloat16* __restrict__ Bhi_e = g_Bhi + wbase;
        const __nv_bfloat16* __restrict__ Blo_e = g_Blo + wbase;

        float acc[4][4][4];
        #pragma unroll
        for (int i = 0; i < 4; ++i)
            #pragma unroll
            for (int j = 0; j < 4; ++j)
                #pragma unroll
                for (int q = 0; q < 4; ++q) acc[i][j][q] = 0.f;

        // ---- stage loader (lambda-ish macro via immediate loop) ----
        auto load_stage = [&](int buf, int kt) {
            const int kof = kt * BK;
            const uint32_t stg = sb + buf * STAGE_BYTES;
            #pragma unroll
            for (int i = 0; i < 8; ++i) {
                const int m = i >> 1;                      // 0..3 matrix id
                const int cidx = ((i & 1) << 8) + tid;     // 0..511
                const int r = cidx >> 2;
                const int c = cidx & 3;
                const uint32_t dst = stg + m * MAT_BYTES + r * PITCH + c * 16;
                const int ke = kof + c * 8;
                const __nv_bfloat16* src;
                if (m == 0)      src = g_Ahi + (size_t)(row0 + r) * K_DIM + ke;
                else if (m == 1) src = g_Alo + (size_t)(row0 + r) * K_DIM + ke;
                else if (m == 2) src = Bhi_e + (size_t)(col0 + r) * K_DIM + ke;
                else             src = Blo_e + (size_t)(col0 + r) * K_DIM + ke;
                cp16(dst, src);
            }
            asm volatile("cp.async.commit_group;" ::: "memory");
        };

        // prologue: stages 0..2
        load_stage(0, 0);
        load_stage(1, 1);
        load_stage(2, 2);

        #pragma unroll 1
        for (int kt = 0; kt < KT; ++kt) {
            const int buf = kt & 3;
            asm volatile("cp.async.wait_group 2;" ::: "memory");
            __syncthreads();

            if (kt + 3 < KT) load_stage((kt + 3) & 3, kt + 3);
            else asm volatile("cp.async.commit_group;" ::: "memory");

            const uint32_t stg = sb + buf * STAGE_BYTES;
            const uint32_t stgAhi = stg;
            const uint32_t stgAlo = stg + MAT_BYTES;
            const uint32_t stgBhi = stg + 2 * MAT_BYTES;
            const uint32_t stgBlo = stg + 3 * MAT_BYTES;

            #pragma unroll
            for (int kh = 0; kh < 2; ++kh) {
                uint32_t ah[4][4], al[4][4], bh[2][4], bl[2][4];
                #pragma unroll
                for (int mt = 0; mt < 4; ++mt) {
                    const uint32_t ao = (uint32_t)((aRow + mt * 16) * PITCH + kh * 32 + aColB);
                    ldsm4(stgAhi + ao, ah[mt]);
                    ldsm4(stgAlo + ao, al[mt]);
                }
                #pragma unroll
                for (int p = 0; p < 2; ++p) {
                    const uint32_t bo = (uint32_t)((bRow + p * 16) * PITCH + kh * 32 + bColB);
                    ldsm4(stgBhi + bo, bh[p]);
                    ldsm4(stgBlo + bo, bl[p]);
                }
                #pragma unroll
                for (int mt = 0; mt < 4; ++mt) {
                    #pragma unroll
                    for (int nt = 0; nt < 4; ++nt) {
                        const uint32_t bh0 = bh[nt >> 1][(nt & 1) * 2];
                        const uint32_t bh1 = bh[nt >> 1][(nt & 1) * 2 + 1];
                        const uint32_t bl0 = bl[nt >> 1][(nt & 1) * 2];
                        const uint32_t bl1 = bl[nt >> 1][(nt & 1) * 2 + 1];
                        mma16816(acc[mt][nt], ah[mt], bh0, bh1);   // hi*hi
                        mma16816(acc[mt][nt], ah[mt], bl0, bl1);   // hi*lo
                        mma16816(acc[mt][nt], al[mt], bh0, bh1);   // lo*hi
                    }
                }
            }
        }

        // ---- epilogue: masked row writes ----
        const int cbase = col0 + warp_n * 32 + (lane & 3) * 2;
        #pragma unroll
        for (int mt = 0; mt < 4; ++mt) {
            const int r0 = row0 + warp_m * 64 + mt * 16 + (lane >> 2);
            const int r1 = r0 + 8;
            const bool w0 = (r0 >= rlo && r0 < rhi);
            const bool w1 = (r1 >= rlo && r1 < rhi);
            #pragma unroll
            for (int nt = 0; nt < 4; ++nt) {
                const int cc = cbase + nt * 8;
                if (w0) *(float2*)&C[(size_t)r0 * N_DIM + cc] =
                            make_float2(acc[mt][nt][0], acc[mt][nt][1]);
                if (w1) *(float2*)&C[(size_t)r1 * N_DIM + cc] =
                            make_float2(acc[mt][nt][2], acc[mt][nt][3]);
            }
        }
        __syncthreads();   // all warps done with smem before next segment's loads
    }
}

extern "C" void kernel_launch(void* const* d_in, const int* in_sizes, int n_in,
                              void* d_out, int out_size)
{
    const float* a = (const float*)d_in[0];    // [M, K]
    const float* b = (const float*)d_in[1];    // [E, N, K]
    const int* seg = nullptr;
    const int* widx = nullptr;
    for (int i = 0; i < n_in; ++i) {
        if (in_sizes[i] == E_SEG + 1)  seg  = (const int*)d_in[i];
        else if (in_sizes[i] == E_SEG) widx = (const int*)d_in[i];
    }
    float* c = (float*)d_out;

    const int nA4 = (M_DIM * K_DIM) / 4;
    const int nB4 = (E_SEG * N_DIM * K_DIM) / 4;
    split_A<<<nA4 / 256, 256>>>((const float4*)a);
    split_B<<<nB4 / 256, 256>>>((const float4*)b);

    cudaFuncSetAttribute(grouped_gemm_hmma,
                         cudaFuncAttributeMaxDynamicSharedMemorySize, SMEM_TOTAL);
    dim3 grid(N_DIM / BN, M_DIM / BM);          // (8, 64) = 512 CTAs
    grouped_gemm_hmma<<<grid, THREADS, SMEM_TOTAL>>>(seg, widx, c);
}

// round 4
// speedup vs baseline: 2.0429x; 1.0085x over previous
#include <cuda_runtime.h>
#include <cuda_bf16.h>
#include <cstdint>

// Grouped GEMM via bf16 3-term split on mma.sync (HMMA, base sm_103 target).
// C[M,N] = A[M,K] @ B[e,N,K]^T per contiguous row segment.
// R4: term-major MMA ordering (no same-acc RAW chains), LDSM/MMA interleave,
//     fused split prepass (1 launch).

constexpr int M_DIM = 8192;
constexpr int K_DIM = 1024;
constexpr int N_DIM = 1024;
constexpr int E_SEG = 8;

#define BM 128
#define BN 128
#define BK 32
#define THREADS 256
constexpr int KT = K_DIM / BK;          // 32 k-chunks
constexpr int PITCH = 80;               // smem row pitch in bytes (40 bf16)
constexpr int MAT_BYTES = 128 * PITCH;  // 10240 per matrix tile
constexpr int STAGE_BYTES = 4 * MAT_BYTES;  // Ahi,Alo,Bhi,Blo = 40960
constexpr int NSTAGE = 4;
constexpr int SMEM_TOTAL = NSTAGE * STAGE_BYTES;  // 163840

// Split storage (bf16)
__device__ __nv_bfloat16 g_Ahi[(size_t)M_DIM * K_DIM];
__device__ __nv_bfloat16 g_Alo[(size_t)M_DIM * K_DIM];
__device__ __nv_bfloat16 g_Bhi[(size_t)E_SEG * N_DIM * K_DIM];
__device__ __nv_bfloat16 g_Blo[(size_t)E_SEG * N_DIM * K_DIM];

constexpr int NA4 = (M_DIM * K_DIM) / 4;          // float4 count of A
constexpr int NB4 = (E_SEG * N_DIM * K_DIM) / 4;  // float4 count of B

// ---------------- fused split prepass ----------------
__device__ __forceinline__ void split4(float4 v, ushort4& h, ushort4& l) {
    __nv_bfloat16 h0 = __float2bfloat16(v.x), h1 = __float2bfloat16(v.y);
    __nv_bfloat16 h2 = __float2bfloat16(v.z), h3 = __float2bfloat16(v.w);
    __nv_bfloat16 l0 = __float2bfloat16(v.x - __bfloat162float(h0));
    __nv_bfloat16 l1 = __float2bfloat16(v.y - __bfloat162float(h1));
    __nv_bfloat16 l2 = __float2bfloat16(v.z - __bfloat162float(h2));
    __nv_bfloat16 l3 = __float2bfloat16(v.w - __bfloat162float(h3));
    h = make_ushort4(__bfloat16_as_ushort(h0), __bfloat16_as_ushort(h1),
                     __bfloat16_as_ushort(h2), __bfloat16_as_ushort(h3));
    l = make_ushort4(__bfloat16_as_ushort(l0), __bfloat16_as_ushort(l1),
                     __bfloat16_as_ushort(l2), __bfloat16_as_ushort(l3));
}

__global__ void __launch_bounds__(256)
split_AB(const float4* __restrict__ A, const float4* __restrict__ B) {
    size_t i = (size_t)blockIdx.x * 256 + threadIdx.x;
    ushort4 h, l;
    if (i < (size_t)NA4) {
        split4(A[i], h, l);
        ((ushort4*)g_Ahi)[i] = h;
        ((ushort4*)g_Alo)[i] = l;
    } else {
        size_t j = i - NA4;
        split4(B[j], h, l);
        ((ushort4*)g_Bhi)[j] = h;
        ((ushort4*)g_Blo)[j] = l;
    }
}

// ---------------- asm helpers ----------------
__device__ __forceinline__ void cp16(uint32_t dst, const void* src) {
    asm volatile("cp.async.cg.shared.global [%0], [%1], 16;" :: "r"(dst), "l"(src));
}
__device__ __forceinline__ void ldsm4(uint32_t addr, uint32_t r[4]) {
    asm volatile("ldmatrix.sync.aligned.m8n8.x4.shared.b16 {%0,%1,%2,%3}, [%4];"
                 : "=r"(r[0]), "=r"(r[1]), "=r"(r[2]), "=r"(r[3]) : "r"(addr));
}
__device__ __forceinline__ void mma16816(float d[4], const uint32_t a[4],
                                         uint32_t b0, uint32_t b1) {
    asm volatile(
        "mma.sync.aligned.m16n8k16.row.col.f32.bf16.bf16.f32 "
        "{%0,%1,%2,%3}, {%4,%5,%6,%7}, {%8,%9}, {%0,%1,%2,%3};"
        : "+f"(d[0]), "+f"(d[1]), "+f"(d[2]), "+f"(d[3])
        : "r"(a[0]), "r"(a[1]), "r"(a[2]), "r"(a[3]), "r"(b0), "r"(b1));
}

// ---------------- main kernel ----------------
__global__ void __launch_bounds__(THREADS, 1)
grouped_gemm_hmma(const int* __restrict__ seg_indptr,
                  const int* __restrict__ widx,
                  float* __restrict__ C)
{
    extern __shared__ char smem[];
    const uint32_t sb = (uint32_t)__cvta_generic_to_shared(smem);
    const int tid = threadIdx.x;
    const int wid = tid >> 5;
    const int lane = tid & 31;
    const int warp_m = wid >> 2;           // 0..1 -> row offset *64
    const int warp_n = wid & 3;            // 0..3 -> col offset *32
    const int row0 = blockIdx.y * BM;
    const int col0 = blockIdx.x * BN;

    // ldmatrix lane addressing (byte offsets within a matrix tile)
    const uint32_t aOff = (uint32_t)((warp_m * 64 + (lane & 15)) * PITCH + (lane >> 4) * 16);
    const uint32_t bOff = (uint32_t)((warp_n * 32 + (lane & 7) + ((lane >> 4) & 1) * 8) * PITCH
                                     + ((lane >> 3) & 1) * 16);

    #pragma unroll 1
    for (int s = 0; s < E_SEG; ++s) {
        const int slo = seg_indptr[s];
        const int shi = seg_indptr[s + 1];
        const int rlo = max(slo, row0);
        const int rhi = min(shi, row0 + BM);
        if (rlo >= rhi) continue;

        const size_t wbase = (size_t)widx[s] * ((size_t)N_DIM * K_DIM);
        const __nv_bfloat16* __restrict__ Bhi_e = g_Bhi + wbase;
        const __nv_bfloat16* __restrict__ Blo_e = g_Blo + wbase;

        float acc[4][4][4];
        #pragma unroll
        for (int i = 0; i < 4; ++i)
            #pragma unroll
            for (int j = 0; j < 4; ++j)
                #pragma unroll
                for (int q = 0; q < 4; ++q) acc[i][j][q] = 0.f;

        auto load_stage = [&](int buf, int kt) {
            const int kof = kt * BK;
            const uint32_t stg = sb + buf * STAGE_BYTES;
            #pragma unroll
            for (int i = 0; i < 8; ++i) {
                const int m = i >> 1;                      // matrix id 0..3
                const int cidx = ((i & 1) << 8) + tid;     // 0..511
                const int r = cidx >> 2;
                const int c = cidx & 3;
                const uint32_t dst = stg + m * MAT_BYTES + r * PITCH + c * 16;
                const int ke = kof + c * 8;
                const __nv_bfloat16* src;
                if (m == 0)      src = g_Ahi + (size_t)(row0 + r) * K_DIM + ke;
                else if (m == 1) src = g_Alo + (size_t)(row0 + r) * K_DIM + ke;
                else if (m == 2) src = Bhi_e + (size_t)(col0 + r) * K_DIM + ke;
                else             src = Blo_e + (size_t)(col0 + r) * K_DIM + ke;
                cp16(dst, src);
            }
            asm volatile("cp.async.commit_group;" ::: "memory");
        };

        // prologue: stages 0..2
        load_stage(0, 0);
        load_stage(1, 1);
        load_stage(2, 2);

        #pragma unroll 1
        for (int kt = 0; kt < KT; ++kt) {
            const int buf = kt & 3;
            asm volatile("cp.async.wait_group 2;" ::: "memory");
            __syncthreads();

            if (kt + 3 < KT) load_stage((kt + 3) & 3, kt + 3);
            else asm volatile("cp.async.commit_group;" ::: "memory");

            const uint32_t stg    = sb + buf * STAGE_BYTES;
            const uint32_t stgAhi = stg;
            const uint32_t stgAlo = stg + MAT_BYTES;
            const uint32_t stgBhi = stg + 2 * MAT_BYTES;
            const uint32_t stgBlo = stg + 3 * MAT_BYTES;

            #pragma unroll
            for (int kh = 0; kh < 2; ++kh) {
                const uint32_t kofB = kh * 32;
                uint32_t ah[4][4], al[4][4], bh[2][4], bl[2][4];

                // hi fragments first...
                #pragma unroll
                for (int mt = 0; mt < 4; ++mt)
                    ldsm4(stgAhi + aOff + mt * (16 * PITCH) + kofB, ah[mt]);
                #pragma unroll
                for (int p = 0; p < 2; ++p)
                    ldsm4(stgBhi + bOff + p * (16 * PITCH) + kofB, bh[p]);
                // ...then lo fragments (complete while hi*hi MMAs run)
                #pragma unroll
                for (int mt = 0; mt < 4; ++mt)
                    ldsm4(stgAlo + aOff + mt * (16 * PITCH) + kofB, al[mt]);
                #pragma unroll
                for (int p = 0; p < 2; ++p)
                    ldsm4(stgBlo + bOff + p * (16 * PITCH) + kofB, bl[p]);

                // Term-major: 16 independent accumulators between revisits.
                #pragma unroll
                for (int mt = 0; mt < 4; ++mt)
                    #pragma unroll
                    for (int nt = 0; nt < 4; ++nt)
                        mma16816(acc[mt][nt], ah[mt],
                                 bh[nt >> 1][(nt & 1) * 2], bh[nt >> 1][(nt & 1) * 2 + 1]);
                #pragma unroll
                for (int mt = 0; mt < 4; ++mt)
                    #pragma unroll
                    for (int nt = 0; nt < 4; ++nt)
                        mma16816(acc[mt][nt], ah[mt],
                                 bl[nt >> 1][(nt & 1) * 2], bl[nt >> 1][(nt & 1) * 2 + 1]);
                #pragma unroll
                for (int mt = 0; mt < 4; ++mt)
                    #pragma unroll
                    for (int nt = 0; nt < 4; ++nt)
                        mma16816(acc[mt][nt], al[mt],
                                 bh[nt >> 1][(nt & 1) * 2], bh[nt >> 1][(nt & 1) * 2 + 1]);
            }
        }

        // ---- epilogue: masked row writes ----
        const int cbase = col0 + warp_n * 32 + (lane & 3) * 2;
        #pragma unroll
        for (int mt = 0; mt < 4; ++mt) {
            const int r0 = row0 + warp_m * 64 + mt * 16 + (lane >> 2);
            const int r1 = r0 + 8;
            const bool w0 = (r0 >= rlo && r0 < rhi);
            const bool w1 = (r1 >= rlo && r1 < rhi);
            #pragma unroll
            for (int nt = 0; nt < 4; ++nt) {
                const int cc = cbase + nt * 8;
                if (w0) *(float2*)&C[(size_t)r0 * N_DIM + cc] =
                            make_float2(acc[mt][nt][0], acc[mt][nt][1]);
                if (w1) *(float2*)&C[(size_t)r1 * N_DIM + cc] =
                            make_float2(acc[mt][nt][2], acc[mt][nt][3]);
            }
        }
        __syncthreads();   // all warps done with smem before next segment's loads
    }
}

extern "C" void kernel_launch(void* const* d_in, const int* in_sizes, int n_in,
                              void* d_out, int out_size)
{
    const float* a = (const float*)d_in[0];    // [M, K]
    const float* b = (const float*)d_in[1];    // [E, N, K]
    const int* seg = nullptr;
    const int* widx = nullptr;
    for (int i = 0; i < n_in; ++i) {
        if (in_sizes[i] == E_SEG + 1)  seg  = (const int*)d_in[i];
        else if (in_sizes[i] == E_SEG) widx = (const int*)d_in[i];
    }
    float* c = (float*)d_out;

    split_AB<<<(NA4 + NB4) / 256, 256>>>((const float4*)a, (const float4*)b);

    cudaFuncSetAttribute(grouped_gemm_hmma,
                         cudaFuncAttributeMaxDynamicSharedMemorySize, SMEM_TOTAL);
    dim3 grid(N_DIM / BN, M_DIM / BM);          // (8, 64) = 512 CTAs
    grouped_gemm_hmma<<<grid, THREADS, SMEM_TOTAL>>>(seg, widx, c);
}

// round 5
// speedup vs baseline: 2.2126x; 1.0831x over previous
#include <cuda_runtime.h>
#include <cuda_bf16.h>
#include <cstdint>

// Grouped GEMM via bf16 3-term split on mma.sync (HMMA, base sm_103 target).
// R5: 2 CTAs/SM (regs<=128 via launch_bounds, 64B-pitch swizzled smem, 3 stages).

constexpr int M_DIM = 8192;
constexpr int K_DIM = 1024;
constexpr int N_DIM = 1024;
constexpr int E_SEG = 8;

#define BM 128
#define BN 128
#define BK 32
#define THREADS 256
constexpr int KT = K_DIM / BK;              // 32 k-chunks
constexpr int MAT_BYTES = 128 * 64;         // 8192: 128 rows x 64B (BK=32 bf16)
constexpr int STAGE_BYTES = 4 * MAT_BYTES;  // Ahi,Alo,Bhi,Blo = 32768
constexpr int NSTAGE = 3;
constexpr int SMEM_TOTAL = NSTAGE * STAGE_BYTES;  // 98304 -> 2 CTAs/SM

// Split storage (bf16)
__device__ __nv_bfloat16 g_Ahi[(size_t)M_DIM * K_DIM];
__device__ __nv_bfloat16 g_Alo[(size_t)M_DIM * K_DIM];
__device__ __nv_bfloat16 g_Bhi[(size_t)E_SEG * N_DIM * K_DIM];
__device__ __nv_bfloat16 g_Blo[(size_t)E_SEG * N_DIM * K_DIM];

constexpr int NA4 = (M_DIM * K_DIM) / 4;
constexpr int NB4 = (E_SEG * N_DIM * K_DIM) / 4;

// ---------------- fused split prepass ----------------
__device__ __forceinline__ void split4(float4 v, ushort4& h, ushort4& l) {
    __nv_bfloat16 h0 = __float2bfloat16(v.x), h1 = __float2bfloat16(v.y);
    __nv_bfloat16 h2 = __float2bfloat16(v.z), h3 = __float2bfloat16(v.w);
    __nv_bfloat16 l0 = __float2bfloat16(v.x - __bfloat162float(h0));
    __nv_bfloat16 l1 = __float2bfloat16(v.y - __bfloat162float(h1));
    __nv_bfloat16 l2 = __float2bfloat16(v.z - __bfloat162float(h2));
    __nv_bfloat16 l3 = __float2bfloat16(v.w - __bfloat162float(h3));
    h = make_ushort4(__bfloat16_as_ushort(h0), __bfloat16_as_ushort(h1),
                     __bfloat16_as_ushort(h2), __bfloat16_as_ushort(h3));
    l = make_ushort4(__bfloat16_as_ushort(l0), __bfloat16_as_ushort(l1),
                     __bfloat16_as_ushort(l2), __bfloat16_as_ushort(l3));
}

__global__ void __launch_bounds__(256)
split_AB(const float4* __restrict__ A, const float4* __restrict__ B) {
    size_t i = (size_t)blockIdx.x * 256 + threadIdx.x;
    ushort4 h, l;
    if (i < (size_t)NA4) {
        split4(A[i], h, l);
        ((ushort4*)g_Ahi)[i] = h;
        ((ushort4*)g_Alo)[i] = l;
    } else {
        size_t j = i - NA4;
        split4(B[j], h, l);
        ((ushort4*)g_Bhi)[j] = h;
        ((ushort4*)g_Blo)[j] = l;
    }
}

// ---------------- asm helpers ----------------
__device__ __forceinline__ void cp16(uint32_t dst, const void* src) {
    asm volatile("cp.async.cg.shared.global [%0], [%1], 16;" :: "r"(dst), "l"(src));
}
__device__ __forceinline__ void ldsm4(uint32_t addr, uint32_t r[4]) {
    asm volatile("ldmatrix.sync.aligned.m8n8.x4.shared.b16 {%0,%1,%2,%3}, [%4];"
                 : "=r"(r[0]), "=r"(r[1]), "=r"(r[2]), "=r"(r[3]) : "r"(addr));
}
__device__ __forceinline__ void mma16816(float d[4], const uint32_t a[4],
                                         uint32_t b0, uint32_t b1) {
    asm volatile(
        "mma.sync.aligned.m16n8k16.row.col.f32.bf16.bf16.f32 "
        "{%0,%1,%2,%3}, {%4,%5,%6,%7}, {%8,%9}, {%0,%1,%2,%3};"
        : "+f"(d[0]), "+f"(d[1]), "+f"(d[2]), "+f"(d[3])
        : "r"(a[0]), "r"(a[1]), "r"(a[2]), "r"(a[3]), "r"(b0), "r"(b1));
}

// 64B-row swizzle: chunk XOR keyed by row bits [2:1]. Conflict-free for
// ldmatrix phases (8 rows hit 8 distinct 16B bank groups) and for cp.async
// stores (consecutive threads write consecutive chunks of one row group).
__device__ __forceinline__ uint32_t swz(uint32_t row, uint32_t colB) {
    return row * 64u + (colB ^ ((row & 6u) << 3));
}

// ---------------- main kernel ----------------
__global__ void __launch_bounds__(THREADS, 2)
grouped_gemm_hmma(const int* __restrict__ seg_indptr,
                  const int* __restrict__ widx,
                  float* __restrict__ C)
{
    extern __shared__ char smem[];
    const uint32_t sb = (uint32_t)__cvta_generic_to_shared(smem);
    const int tid = threadIdx.x;
    const int wid = tid >> 5;
    const int lane = tid & 31;
    const int warp_m = wid >> 2;           // 0..1 -> row offset *64
    const int warp_n = wid & 3;            // 0..3 -> col offset *32
    const int row0 = blockIdx.y * BM;
    const int col0 = blockIdx.x * BN;

    // ldmatrix lane rows (fixed per thread)
    const uint32_t aRow = (uint32_t)(warp_m * 64 + (lane & 15));
    const uint32_t bRow = (uint32_t)(warp_n * 32 + (lane & 7) + ((lane >> 4) & 1) * 8);
    const uint32_t aSel = (uint32_t)((lane >> 4) * 16);        // 0 or 16
    const uint32_t bSel = (uint32_t)(((lane >> 3) & 1) * 16);  // 0 or 16

    // cp.async store mapping (fixed per thread): thread handles chunk pairs.
    const uint32_t ldR = (uint32_t)(tid >> 2);     // 0..63 (plus +64 on 2nd half)
    const uint32_t ldC = (uint32_t)(tid & 3);      // chunk 0..3

    #pragma unroll 1
    for (int s = 0; s < E_SEG; ++s) {
        const int slo = seg_indptr[s];
        const int shi = seg_indptr[s + 1];
        const int rlo = max(slo, row0);
        const int rhi = min(shi, row0 + BM);
        if (rlo >= rhi) continue;

        const size_t wbase = (size_t)widx[s] * ((size_t)N_DIM * K_DIM);
        const __nv_bfloat16* __restrict__ Bhi_e = g_Bhi + wbase;
        const __nv_bfloat16* __restrict__ Blo_e = g_Blo + wbase;

        float acc[4][4][4];
        #pragma unroll
        for (int i = 0; i < 4; ++i)
            #pragma unroll
            for (int j = 0; j < 4; ++j)
                #pragma unroll
                for (int q = 0; q < 4; ++q) acc[i][j][q] = 0.f;

        auto load_stage = [&](int buf, int kt) {
            const int ke = kt * BK + (int)ldC * 8;
            const uint32_t stg = sb + buf * STAGE_BYTES;
            #pragma unroll
            for (int half = 0; half < 2; ++half) {
                const uint32_t r = ldR + half * 64;
                const uint32_t so = swz(r, ldC * 16);
                cp16(stg + so,                 g_Ahi + (size_t)(row0 + r) * K_DIM + ke);
                cp16(stg + MAT_BYTES + so,     g_Alo + (size_t)(row0 + r) * K_DIM + ke);
                cp16(stg + 2 * MAT_BYTES + so, Bhi_e + (size_t)(col0 + r) * K_DIM + ke);
                cp16(stg + 3 * MAT_BYTES + so, Blo_e + (size_t)(col0 + r) * K_DIM + ke);
            }
            asm volatile("cp.async.commit_group;" ::: "memory");
        };

        // prologue: stages 0,1
        load_stage(0, 0);
        load_stage(1, 1);

        #pragma unroll 1
        for (int kt = 0; kt < KT; ++kt) {
            const int buf = kt % 3;
            asm volatile("cp.async.wait_group 1;" ::: "memory");
            __syncthreads();

            if (kt + 2 < KT) load_stage((kt + 2) % 3, kt + 2);
            else asm volatile("cp.async.commit_group;" ::: "memory");

            const uint32_t stg    = sb + buf * STAGE_BYTES;
            const uint32_t stgAhi = stg;
            const uint32_t stgAlo = stg + MAT_BYTES;
            const uint32_t stgBhi = stg + 2 * MAT_BYTES;
            const uint32_t stgBlo = stg + 3 * MAT_BYTES;

            #pragma unroll
            for (int kh = 0; kh < 2; ++kh) {
                const uint32_t aCB = (uint32_t)(kh * 32) + aSel;
                const uint32_t bCB = (uint32_t)(kh * 32) + bSel;

                uint32_t ah[4][4], bh[2][4];
                #pragma unroll
                for (int mt = 0; mt < 4; ++mt)
                    ldsm4(stgAhi + swz(aRow + mt * 16, aCB), ah[mt]);
                #pragma unroll
                for (int p = 0; p < 2; ++p)
                    ldsm4(stgBhi + swz(bRow + p * 16, bCB), bh[p]);

                #pragma unroll
                for (int mt = 0; mt < 4; ++mt)
                    #pragma unroll
                    for (int nt = 0; nt < 4; ++nt)
                        mma16816(acc[mt][nt], ah[mt],
                                 bh[nt >> 1][(nt & 1) * 2], bh[nt >> 1][(nt & 1) * 2 + 1]);

                uint32_t bl[2][4];
                #pragma unroll
                for (int p = 0; p < 2; ++p)
                    ldsm4(stgBlo + swz(bRow + p * 16, bCB), bl[p]);

                #pragma unroll
                for (int mt = 0; mt < 4; ++mt)
                    #pragma unroll
                    for (int nt = 0; nt < 4; ++nt)
                        mma16816(acc[mt][nt], ah[mt],
                                 bl[nt >> 1][(nt & 1) * 2], bl[nt >> 1][(nt & 1) * 2 + 1]);

                uint32_t al[4][4];
                #pragma unroll
                for (int mt = 0; mt < 4; ++mt)
                    ldsm4(stgAlo + swz(aRow + mt * 16, aCB), al[mt]);

                #pragma unroll
                for (int mt = 0; mt < 4; ++mt)
                    #pragma unroll
                    for (int nt = 0; nt < 4; ++nt)
                        mma16816(acc[mt][nt], al[mt],
                                 bh[nt >> 1][(nt & 1) * 2], bh[nt >> 1][(nt & 1) * 2 + 1]);
            }
        }

        // ---- epilogue: masked row writes ----
        const int cbase = col0 + warp_n * 32 + (lane & 3) * 2;
        #pragma unroll
        for (int mt = 0; mt < 4; ++mt) {
            const int r0 = row0 + warp_m * 64 + mt * 16 + (lane >> 2);
            const int r1 = r0 + 8;
            const bool w0 = (r0 >= rlo && r0 < rhi);
            const bool w1 = (r1 >= rlo && r1 < rhi);
            #pragma unroll
            for (int nt = 0; nt < 4; ++nt) {
                const int cc = cbase + nt * 8;
                if (w0) *(float2*)&C[(size_t)r0 * N_DIM + cc] =
                            make_float2(acc[mt][nt][0], acc[mt][nt][1]);
                if (w1) *(float2*)&C[(size_t)r1 * N_DIM + cc] =
                            make_float2(acc[mt][nt][2], acc[mt][nt][3]);
            }
        }
        __syncthreads();   // all warps done with smem before next segment's loads
    }
}

extern "C" void kernel_launch(void* const* d_in, const int* in_sizes, int n_in,
                              void* d_out, int out_size)
{
    const float* a = (const float*)d_in[0];    // [M, K]
    const float* b = (const float*)d_in[1];    // [E, N, K]
    const int* seg = nullptr;
    const int* widx = nullptr;
    for (int i = 0; i < n_in; ++i) {
        if (in_sizes[i] == E_SEG + 1)  seg  = (const int*)d_in[i];
        else if (in_sizes[i] == E_SEG) widx = (const int*)d_in[i];
    }
    float* c = (float*)d_out;

    split_AB<<<(NA4 + NB4) / 256, 256>>>((const float4*)a, (const float4*)b);

    cudaFuncSetAttribute(grouped_gemm_hmma,
                         cudaFuncAttributeMaxDynamicSharedMemorySize, SMEM_TOTAL);
    dim3 grid(N_DIM / BN, M_DIM / BM);          // (8, 64) = 512 CTAs
    grouped_gemm_hmma<<<grid, THREADS, SMEM_TOTAL>>>(seg, widx, c);
}

// round 6
// speedup vs baseline: 2.6234x; 1.1857x over previous
#include <cuda_runtime.h>
#include <cuda_bf16.h>
#include <cstdint>

// Grouped GEMM via bf16 3-term split on mma.sync (HMMA, base sm_103 target).
// R6: mbarrier full/empty pipeline (no per-kt __syncthreads convoy),
//     2 CTAs/SM, 3-stage cp.async, flattened (item, kt) work stream.

constexpr int M_DIM = 8192;
constexpr int K_DIM = 1024;
constexpr int N_DIM = 1024;
constexpr int E_SEG = 8;

#define BM 128
#define BN 128
#define BK 32
#define THREADS 256
constexpr int KT = K_DIM / BK;              // 32 k-chunks
constexpr int MAT_BYTES = 128 * 64;         // 8192: 128 rows x 64B
constexpr int STAGE_BYTES = 4 * MAT_BYTES;  // Ahi,Alo,Bhi,Blo = 32768
constexpr int NSTAGE = 3;
constexpr int MBAR_OFF = NSTAGE * STAGE_BYTES;   // 98304
constexpr int SMEM_TOTAL = MBAR_OFF + 64;        // + mbar block

// Split storage (bf16)
__device__ __nv_bfloat16 g_Ahi[(size_t)M_DIM * K_DIM];
__device__ __nv_bfloat16 g_Alo[(size_t)M_DIM * K_DIM];
__device__ __nv_bfloat16 g_Bhi[(size_t)E_SEG * N_DIM * K_DIM];
__device__ __nv_bfloat16 g_Blo[(size_t)E_SEG * N_DIM * K_DIM];

constexpr int NA4 = (M_DIM * K_DIM) / 4;
constexpr int NB4 = (E_SEG * N_DIM * K_DIM) / 4;

// ---------------- fused split prepass ----------------
__device__ __forceinline__ void split4(float4 v, ushort4& h, ushort4& l) {
    __nv_bfloat16 h0 = __float2bfloat16(v.x), h1 = __float2bfloat16(v.y);
    __nv_bfloat16 h2 = __float2bfloat16(v.z), h3 = __float2bfloat16(v.w);
    __nv_bfloat16 l0 = __float2bfloat16(v.x - __bfloat162float(h0));
    __nv_bfloat16 l1 = __float2bfloat16(v.y - __bfloat162float(h1));
    __nv_bfloat16 l2 = __float2bfloat16(v.z - __bfloat162float(h2));
    __nv_bfloat16 l3 = __float2bfloat16(v.w - __bfloat162float(h3));
    h = make_ushort4(__bfloat16_as_ushort(h0), __bfloat16_as_ushort(h1),
                     __bfloat16_as_ushort(h2), __bfloat16_as_ushort(h3));
    l = make_ushort4(__bfloat16_as_ushort(l0), __bfloat16_as_ushort(l1),
                     __bfloat16_as_ushort(l2), __bfloat16_as_ushort(l3));
}

__global__ void __launch_bounds__(256)
split_AB(const float4* __restrict__ A, const float4* __restrict__ B) {
    size_t i = (size_t)blockIdx.x * 256 + threadIdx.x;
    ushort4 h, l;
    if (i < (size_t)NA4) {
        split4(A[i], h, l);
        ((ushort4*)g_Ahi)[i] = h;
        ((ushort4*)g_Alo)[i] = l;
    } else {
        size_t j = i - NA4;
        split4(B[j], h, l);
        ((ushort4*)g_Bhi)[j] = h;
        ((ushort4*)g_Blo)[j] = l;
    }
}

// ---------------- asm helpers ----------------
__device__ __forceinline__ void cp16(uint32_t dst, const void* src) {
    asm volatile("cp.async.cg.shared.global [%0], [%1], 16;" :: "r"(dst), "l"(src));
}
__device__ __forceinline__ void ldsm4(uint32_t addr, uint32_t r[4]) {
    asm volatile("ldmatrix.sync.aligned.m8n8.x4.shared.b16 {%0,%1,%2,%3}, [%4];"
                 : "=r"(r[0]), "=r"(r[1]), "=r"(r[2]), "=r"(r[3]) : "r"(addr));
}
__device__ __forceinline__ void mma16816(float d[4], const uint32_t a[4],
                                         uint32_t b0, uint32_t b1) {
    asm volatile(
        "mma.sync.aligned.m16n8k16.row.col.f32.bf16.bf16.f32 "
        "{%0,%1,%2,%3}, {%4,%5,%6,%7}, {%8,%9}, {%0,%1,%2,%3};"
        : "+f"(d[0]), "+f"(d[1]), "+f"(d[2]), "+f"(d[3])
        : "r"(a[0]), "r"(a[1]), "r"(a[2]), "r"(a[3]), "r"(b0), "r"(b1));
}
__device__ __forceinline__ void mbar_init(uint32_t m, uint32_t cnt) {
    asm volatile("mbarrier.init.shared.b64 [%0], %1;" :: "r"(m), "r"(cnt) : "memory");
}
__device__ __forceinline__ void mbar_arrive(uint32_t m) {
    asm volatile("mbarrier.arrive.shared.b64 _, [%0];" :: "r"(m) : "memory");
}
__device__ __forceinline__ void cpasync_arrive(uint32_t m) {
    asm volatile("cp.async.mbarrier.arrive.noinc.shared.b64 [%0];" :: "r"(m) : "memory");
}
__device__ __forceinline__ void mbar_wait(uint32_t m, uint32_t parity) {
    uint32_t done;
    asm volatile("{\n\t.reg .pred p;\n\t"
                 "mbarrier.try_wait.parity.acquire.cta.shared::cta.b64 p, [%1], %2;\n\t"
                 "selp.b32 %0, 1, 0, p;\n\t}" : "=r"(done) : "r"(m), "r"(parity) : "memory");
    if (!done) {
        asm volatile("{\n\t.reg .pred P1;\n\t"
                     "W_%=:\n\t"
                     "mbarrier.try_wait.parity.acquire.cta.shared::cta.b64 P1, [%0], %1, 0x989680;\n\t"
                     "@P1 bra.uni D_%=;\n\t"
                     "bra.uni W_%=;\n\t"
                     "D_%=:\n\t}" :: "r"(m), "r"(parity) : "memory");
    }
}

// 64B-row swizzle (conflict-free for ldmatrix phases & cp.async stores).
__device__ __forceinline__ uint32_t swz(uint32_t row, uint32_t colB) {
    return row * 64u + (colB ^ ((row & 6u) << 3));
}

// ---------------- main kernel ----------------
__global__ void __launch_bounds__(THREADS, 2)
grouped_gemm_hmma(const int* __restrict__ seg_indptr,
                  const int* __restrict__ widx,
                  float* __restrict__ C)
{
    extern __shared__ char smem[];
    const uint32_t sb = (uint32_t)__cvta_generic_to_shared(smem);
    const int tid = threadIdx.x;
    const int wid = tid >> 5;
    const int lane = tid & 31;
    const int warp_m = wid >> 2;
    const int warp_n = wid & 3;
    const int row0 = blockIdx.y * BM;
    const int col0 = blockIdx.x * BN;

    const uint32_t mbF = sb + MBAR_OFF;        // full[i]  at +8*i
    const uint32_t mbE = sb + MBAR_OFF + 24;   // empty[i] at +8*i

    if (tid == 0) {
        #pragma unroll
        for (int i = 0; i < 3; ++i) {
            mbar_init(mbF + i * 8, 256);   // one .noinc arrival per thread
            mbar_init(mbE + i * 8, 8);     // one arrival per warp
        }
    }
    __syncthreads();

    // ldmatrix lane addressing
    const uint32_t aRow = (uint32_t)(warp_m * 64 + (lane & 15));
    const uint32_t bRow = (uint32_t)(warp_n * 32 + (lane & 7) + ((lane >> 4) & 1) * 8);
    const uint32_t aSel = (uint32_t)((lane >> 4) * 16);
    const uint32_t bSel = (uint32_t)(((lane >> 3) & 1) * 16);

    // cp.async store mapping
    const uint32_t ldR = (uint32_t)(tid >> 2);
    const uint32_t ldC = (uint32_t)(tid & 3);

    // ---- enumerate work items (segments intersecting this row band) ----
    int nIt = 0;
    int iRlo[E_SEG], iRhi[E_SEG];
    const __nv_bfloat16 *iBh[E_SEG], *iBl[E_SEG];
    #pragma unroll 1
    for (int s = 0; s < E_SEG; ++s) {
        const int rlo = max(seg_indptr[s], row0);
        const int rhi = min(seg_indptr[s + 1], row0 + BM);
        if (rlo < rhi) {
            const size_t wbase = (size_t)widx[s] * ((size_t)N_DIM * K_DIM);
            iRlo[nIt] = rlo; iRhi[nIt] = rhi;
            iBh[nIt] = g_Bhi + wbase; iBl[nIt] = g_Blo + wbase;
            ++nIt;
        }
    }
    const int total = nIt * KT;

    int pst = 0, pph = 1;   // producer cursor (phase 1: first empty-wait passes)
    int cst = 0, cph = 0;   // consumer cursor

    auto produce = [&](int q) {
        const int it = q >> 5;
        const int kt = q & 31;
        mbar_wait(mbE + pst * 8, (uint32_t)pph);
        const uint32_t stg = sb + pst * STAGE_BYTES;
        const int ke = kt * BK + (int)ldC * 8;
        const __nv_bfloat16* __restrict__ bh = iBh[it];
        const __nv_bfloat16* __restrict__ bl = iBl[it];
        #pragma unroll
        for (int half = 0; half < 2; ++half) {
            const uint32_t r = ldR + half * 64;
            const uint32_t so = swz(r, ldC * 16);
            cp16(stg + so,                 g_Ahi + (size_t)(row0 + r) * K_DIM + ke);
            cp16(stg + MAT_BYTES + so,     g_Alo + (size_t)(row0 + r) * K_DIM + ke);
            cp16(stg + 2 * MAT_BYTES + so, bh + (size_t)(col0 + r) * K_DIM + ke);
            cp16(stg + 3 * MAT_BYTES + so, bl + (size_t)(col0 + r) * K_DIM + ke);
        }
        cpasync_arrive(mbF + pst * 8);
        if (++pst == 3) { pst = 0; pph ^= 1; }
    };

    float acc[4][4][4];
    #pragma unroll
    for (int i = 0; i < 4; ++i)
        #pragma unroll
        for (int j = 0; j < 4; ++j)
            #pragma unroll
            for (int q = 0; q < 4; ++q) acc[i][j][q] = 0.f;

    // prologue: stages 0,1
    produce(0);
    produce(1);

    #pragma unroll 1
    for (int q = 0; q < total; ++q) {
        mbar_wait(mbF + cst * 8, (uint32_t)cph);
        if (q + 2 < total) produce(q + 2);

        const uint32_t stg    = sb + cst * STAGE_BYTES;
        const uint32_t stgAhi = stg;
        const uint32_t stgAlo = stg + MAT_BYTES;
        const uint32_t stgBhi = stg + 2 * MAT_BYTES;
        const uint32_t stgBlo = stg + 3 * MAT_BYTES;

        #pragma unroll
        for (int kh = 0; kh < 2; ++kh) {
            const uint32_t aCB = (uint32_t)(kh * 32) + aSel;
            const uint32_t bCB = (uint32_t)(kh * 32) + bSel;

            uint32_t ah[4][4], bh[2][4];
            #pragma unroll
            for (int mt = 0; mt < 4; ++mt)
                ldsm4(stgAhi + swz(aRow + mt * 16, aCB), ah[mt]);
            #pragma unroll
            for (int p = 0; p < 2; ++p)
                ldsm4(stgBhi + swz(bRow + p * 16, bCB), bh[p]);

            #pragma unroll
            for (int mt = 0; mt < 4; ++mt)
                #pragma unroll
                for (int nt = 0; nt < 4; ++nt)
                    mma16816(acc[mt][nt], ah[mt],
                             bh[nt >> 1][(nt & 1) * 2], bh[nt >> 1][(nt & 1) * 2 + 1]);

            uint32_t bl[2][4];
            #pragma unroll
            for (int p = 0; p < 2; ++p)
                ldsm4(stgBlo + swz(bRow + p * 16, bCB), bl[p]);

            #pragma unroll
            for (int mt = 0; mt < 4; ++mt)
                #pragma unroll
                for (int nt = 0; nt < 4; ++nt)
                    mma16816(acc[mt][nt], ah[mt],
                             bl[nt >> 1][(nt & 1) * 2], bl[nt >> 1][(nt & 1) * 2 + 1]);

            uint32_t al[4][4];
            #pragma unroll
            for (int mt = 0; mt < 4; ++mt)
                ldsm4(stgAlo + swz(aRow + mt * 16, aCB), al[mt]);

            #pragma unroll
            for (int mt = 0; mt < 4; ++mt)
                #pragma unroll
                for (int nt = 0; nt < 4; ++nt)
                    mma16816(acc[mt][nt], al[mt],
                             bh[nt >> 1][(nt & 1) * 2], bh[nt >> 1][(nt & 1) * 2 + 1]);
        }

        // Stage consumed: every LDSM result was read by an issued MMA, so the
        // smem reads are complete; one arrival per warp frees the stage.
        if (lane == 0) mbar_arrive(mbE + cst * 8);
        if (++cst == 3) { cst = 0; cph ^= 1; }

        // item boundary -> epilogue + acc reset
        if ((q & 31) == 31) {
            const int it = q >> 5;
            const int rloI = iRlo[it], rhiI = iRhi[it];
            const int cbase = col0 + warp_n * 32 + (lane & 3) * 2;
            #pragma unroll
            for (int mt = 0; mt < 4; ++mt) {
                const int r0 = row0 + warp_m * 64 + mt * 16 + (lane >> 2);
                const int r1 = r0 + 8;
                const bool w0 = (r0 >= rloI && r0 < rhiI);
                const bool w1 = (r1 >= rloI && r1 < rhiI);
                #pragma unroll
                for (int nt = 0; nt < 4; ++nt) {
                    const int cc = cbase + nt * 8;
                    if (w0) *(float2*)&C[(size_t)r0 * N_DIM + cc] =
                                make_float2(acc[mt][nt][0], acc[mt][nt][1]);
                    if (w1) *(float2*)&C[(size_t)r1 * N_DIM + cc] =
                                make_float2(acc[mt][nt][2], acc[mt][nt][3]);
                }
            }
            #pragma unroll
            for (int i = 0; i < 4; ++i)
                #pragma unroll
                for (int j = 0; j < 4; ++j)
                    #pragma unroll
                    for (int p = 0; p < 4; ++p) acc[i][j][p] = 0.f;
        }
    }
}

extern "C" void kernel_launch(void* const* d_in, const int* in_sizes, int n_in,
                              void* d_out, int out_size)
{
    const float* a = (const float*)d_in[0];    // [M, K]
    const float* b = (const float*)d_in[1];    // [E, N, K]
    const int* seg = nullptr;
    const int* widx = nullptr;
    for (int i = 0; i < n_in; ++i) {
        if (in_sizes[i] == E_SEG + 1)  seg  = (const int*)d_in[i];
        else if (in_sizes[i] == E_SEG) widx = (const int*)d_in[i];
    }
    float* c = (float*)d_out;

    split_AB<<<(NA4 + NB4) / 256, 256>>>((const float4*)a, (const float4*)b);

    cudaFuncSetAttribute(grouped_gemm_hmma,
                         cudaFuncAttributeMaxDynamicSharedMemorySize, SMEM_TOTAL);
    dim3 grid(N_DIM / BN, M_DIM / BM);          // (8, 64) = 512 CTAs
    grouped_gemm_hmma<<<grid, THREADS, SMEM_TOTAL>>>(seg, widx, c);
}

// round 7
// speedup vs baseline: 3.2144x; 1.2253x over previous
#include <cuda_runtime.h>
#include <cuda_fp16.h>
#include <cstdint>

// Grouped GEMM via fp16 2-term split on mma.sync (base sm_103 target).
// C = Ahi@Bh^T + Alo@Bh^T  where A = Ahi + Alo (fp16 hi/lo), Bh = fp16(B).
// Error: only B's fp16 rounding (~2^-12 rel) -> global rel_err ~1e-4 << 1e-3.
// R7: 2 terms (-33% MMA work), 4-stage mbarrier cp.async pipeline, 2 CTAs/SM.

constexpr int M_DIM = 8192;
constexpr int K_DIM = 1024;
constexpr int N_DIM = 1024;
constexpr int E_SEG = 8;

#define BM 128
#define BN 128
#define BK 32
#define THREADS 256
constexpr int KT = K_DIM / BK;              // 32 k-chunks
constexpr int MAT_BYTES = 128 * 64;         // 8192: 128 rows x 64B (32 fp16)
constexpr int STAGE_BYTES = 3 * MAT_BYTES;  // Ahi, Alo, Bh = 24576
constexpr int NSTAGE = 4;
constexpr int MBAR_OFF = NSTAGE * STAGE_BYTES;   // 98304
constexpr int SMEM_TOTAL = MBAR_OFF + 64;

// Split storage (fp16)
__device__ __half g_Ahi[(size_t)M_DIM * K_DIM];
__device__ __half g_Alo[(size_t)M_DIM * K_DIM];
__device__ __half g_Bh [(size_t)E_SEG * N_DIM * K_DIM];

constexpr int NA4 = (M_DIM * K_DIM) / 4;
constexpr int NB4 = (E_SEG * N_DIM * K_DIM) / 4;

// ---------------- fused split prepass ----------------
__global__ void __launch_bounds__(256)
split_AB(const float4* __restrict__ A, const float4* __restrict__ B) {
    size_t i = (size_t)blockIdx.x * 256 + threadIdx.x;
    if (i < (size_t)NA4) {
        float4 v = A[i];
        __half h0 = __float2half(v.x), h1 = __float2half(v.y);
        __half h2 = __float2half(v.z), h3 = __float2half(v.w);
        __half l0 = __float2half(v.x - __half2float(h0));
        __half l1 = __float2half(v.y - __half2float(h1));
        __half l2 = __float2half(v.z - __half2float(h2));
        __half l3 = __float2half(v.w - __half2float(h3));
        ((ushort4*)g_Ahi)[i] = make_ushort4(__half_as_ushort(h0), __half_as_ushort(h1),
                                            __half_as_ushort(h2), __half_as_ushort(h3));
        ((ushort4*)g_Alo)[i] = make_ushort4(__half_as_ushort(l0), __half_as_ushort(l1),
                                            __half_as_ushort(l2), __half_as_ushort(l3));
    } else {
        size_t j = i - NA4;
        float4 v = B[j];
        ((ushort4*)g_Bh)[j] = make_ushort4(
            __half_as_ushort(__float2half(v.x)), __half_as_ushort(__float2half(v.y)),
            __half_as_ushort(__float2half(v.z)), __half_as_ushort(__float2half(v.w)));
    }
}

// ---------------- asm helpers ----------------
__device__ __forceinline__ void cp16(uint32_t dst, const void* src) {
    asm volatile("cp.async.cg.shared.global [%0], [%1], 16;" :: "r"(dst), "l"(src));
}
__device__ __forceinline__ void ldsm4(uint32_t addr, uint32_t r[4]) {
    asm volatile("ldmatrix.sync.aligned.m8n8.x4.shared.b16 {%0,%1,%2,%3}, [%4];"
                 : "=r"(r[0]), "=r"(r[1]), "=r"(r[2]), "=r"(r[3]) : "r"(addr));
}
__device__ __forceinline__ void mma16816(float d[4], const uint32_t a[4],
                                         uint32_t b0, uint32_t b1) {
    asm volatile(
        "mma.sync.aligned.m16n8k16.row.col.f32.f16.f16.f32 "
        "{%0,%1,%2,%3}, {%4,%5,%6,%7}, {%8,%9}, {%0,%1,%2,%3};"
        : "+f"(d[0]), "+f"(d[1]), "+f"(d[2]), "+f"(d[3])
        : "r"(a[0]), "r"(a[1]), "r"(a[2]), "r"(a[3]), "r"(b0), "r"(b1));
}
__device__ __forceinline__ void mbar_init(uint32_t m, uint32_t cnt) {
    asm volatile("mbarrier.init.shared.b64 [%0], %1;" :: "r"(m), "r"(cnt) : "memory");
}
__device__ __forceinline__ void mbar_arrive(uint32_t m) {
    asm volatile("mbarrier.arrive.shared.b64 _, [%0];" :: "r"(m) : "memory");
}
__device__ __forceinline__ void cpasync_arrive(uint32_t m) {
    asm volatile("cp.async.mbarrier.arrive.noinc.shared.b64 [%0];" :: "r"(m) : "memory");
}
__device__ __forceinline__ void mbar_wait(uint32_t m, uint32_t parity) {
    uint32_t done;
    asm volatile("{\n\t.reg .pred p;\n\t"
                 "mbarrier.try_wait.parity.acquire.cta.shared::cta.b64 p, [%1], %2;\n\t"
                 "selp.b32 %0, 1, 0, p;\n\t}" : "=r"(done) : "r"(m), "r"(parity) : "memory");
    if (!done) {
        asm volatile("{\n\t.reg .pred P1;\n\t"
                     "W_%=:\n\t"
                     "mbarrier.try_wait.parity.acquire.cta.shared::cta.b64 P1, [%0], %1, 0x989680;\n\t"
                     "@P1 bra.uni D_%=;\n\t"
                     "bra.uni W_%=;\n\t"
                     "D_%=:\n\t}" :: "r"(m), "r"(parity) : "memory");
    }
}

// 64B-row swizzle (conflict-free for ldmatrix phases & cp.async stores).
__device__ __forceinline__ uint32_t swz(uint32_t row, uint32_t colB) {
    return row * 64u + (colB ^ ((row & 6u) << 3));
}

// ---------------- main kernel ----------------
__global__ void __launch_bounds__(THREADS, 2)
grouped_gemm_hmma(const int* __restrict__ seg_indptr,
                  const int* __restrict__ widx,
                  float* __restrict__ C)
{
    extern __shared__ char smem[];
    const uint32_t sb = (uint32_t)__cvta_generic_to_shared(smem);
    const int tid = threadIdx.x;
    const int wid = tid >> 5;
    const int lane = tid & 31;
    const int warp_m = wid >> 2;
    const int warp_n = wid & 3;
    const int row0 = blockIdx.y * BM;
    const int col0 = blockIdx.x * BN;

    const uint32_t mbF = sb + MBAR_OFF;        // full[i]  at +8*i (4 stages)
    const uint32_t mbE = sb + MBAR_OFF + 32;   // empty[i] at +8*i

    if (tid == 0) {
        #pragma unroll
        for (int i = 0; i < NSTAGE; ++i) {
            mbar_init(mbF + i * 8, 256);   // one .noinc arrival per thread
            mbar_init(mbE + i * 8, 8);     // one arrival per warp
        }
    }
    __syncthreads();

    // ldmatrix lane addressing
    const uint32_t aRow = (uint32_t)(warp_m * 64 + (lane & 15));
    const uint32_t bRow = (uint32_t)(warp_n * 32 + (lane & 7) + ((lane >> 4) & 1) * 8);
    const uint32_t aSel = (uint32_t)((lane >> 4) * 16);
    const uint32_t bSel = (uint32_t)(((lane >> 3) & 1) * 16);

    // cp.async store mapping
    const uint32_t ldR = (uint32_t)(tid >> 2);
    const uint32_t ldC = (uint32_t)(tid & 3);

    // ---- enumerate work items (segments intersecting this row band) ----
    int nIt = 0;
    int iRlo[E_SEG], iRhi[E_SEG];
    const __half* iB[E_SEG];
    #pragma unroll 1
    for (int s = 0; s < E_SEG; ++s) {
        const int rlo = max(seg_indptr[s], row0);
        const int rhi = min(seg_indptr[s + 1], row0 + BM);
        if (rlo < rhi) {
            iRlo[nIt] = rlo; iRhi[nIt] = rhi;
            iB[nIt] = g_Bh + (size_t)widx[s] * ((size_t)N_DIM * K_DIM);
            ++nIt;
        }
    }
    const int total = nIt * KT;

    int pst = 0, pph = 1;   // producer cursor
    int cst = 0, cph = 0;   // consumer cursor

    auto produce = [&](int q) {
        const int it = q >> 5;
        const int kt = q & 31;
        mbar_wait(mbE + pst * 8, (uint32_t)pph);
        const uint32_t stg = sb + pst * STAGE_BYTES;
        const int ke = kt * BK + (int)ldC * 8;
        const __half* __restrict__ be = iB[it];
        #pragma unroll
        for (int half = 0; half < 2; ++half) {
            const uint32_t r = ldR + half * 64;
            const uint32_t so = swz(r, ldC * 16);
            cp16(stg + so,                 g_Ahi + (size_t)(row0 + r) * K_DIM + ke);
            cp16(stg + MAT_BYTES + so,     g_Alo + (size_t)(row0 + r) * K_DIM + ke);
            cp16(stg + 2 * MAT_BYTES + so, be + (size_t)(col0 + r) * K_DIM + ke);
        }
        cpasync_arrive(mbF + pst * 8);
        if (++pst == NSTAGE) { pst = 0; pph ^= 1; }
    };

    float acc[4][4][4];
    #pragma unroll
    for (int i = 0; i < 4; ++i)
        #pragma unroll
        for (int j = 0; j < 4; ++j)
            #pragma unroll
            for (int q = 0; q < 4; ++q) acc[i][j][q] = 0.f;

    // prologue: 3 stages ahead
    produce(0);
    if (total > 1) produce(1);
    if (total > 2) produce(2);

    #pragma unroll 1
    for (int q = 0; q < total; ++q) {
        mbar_wait(mbF + cst * 8, (uint32_t)cph);
        if (q + 3 < total) produce(q + 3);

        const uint32_t stg    = sb + cst * STAGE_BYTES;
        const uint32_t stgAhi = stg;
        const uint32_t stgAlo = stg + MAT_BYTES;
        const uint32_t stgBh  = stg + 2 * MAT_BYTES;

        #pragma unroll
        for (int kh = 0; kh < 2; ++kh) {
            const uint32_t aCB = (uint32_t)(kh * 32) + aSel;
            const uint32_t bCB = (uint32_t)(kh * 32) + bSel;

            uint32_t ah[4][4], bh[2][4];
            #pragma unroll
            for (int mt = 0; mt < 4; ++mt)
                ldsm4(stgAhi + swz(aRow + mt * 16, aCB), ah[mt]);
            #pragma unroll
            for (int p = 0; p < 2; ++p)
                ldsm4(stgBh + swz(bRow + p * 16, bCB), bh[p]);

            #pragma unroll
            for (int mt = 0; mt < 4; ++mt)
                #pragma unroll
                for (int nt = 0; nt < 4; ++nt)
                    mma16816(acc[mt][nt], ah[mt],
                             bh[nt >> 1][(nt & 1) * 2], bh[nt >> 1][(nt & 1) * 2 + 1]);

            uint32_t al[4][4];
            #pragma unroll
            for (int mt = 0; mt < 4; ++mt)
                ldsm4(stgAlo + swz(aRow + mt * 16, aCB), al[mt]);

            #pragma unroll
            for (int mt = 0; mt < 4; ++mt)
                #pragma unroll
                for (int nt = 0; nt < 4; ++nt)
                    mma16816(acc[mt][nt], al[mt],
                             bh[nt >> 1][(nt & 1) * 2], bh[nt >> 1][(nt & 1) * 2 + 1]);
        }

        // Stage consumed (in-order issue: LDSM results all fed into issued MMAs).
        if (lane == 0) mbar_arrive(mbE + cst * 8);
        if (++cst == NSTAGE) { cst = 0; cph ^= 1; }

        // item boundary -> epilogue + acc reset
        if ((q & 31) == 31) {
            const int it = q >> 5;
            const int rloI = iRlo[it], rhiI = iRhi[it];
            const int cbase = col0 + warp_n * 32 + (lane & 3) * 2;
            #pragma unroll
            for (int mt = 0; mt < 4; ++mt) {
                const int r0 = row0 + warp_m * 64 + mt * 16 + (lane >> 2);
                const int r1 = r0 + 8;
                const bool w0 = (r0 >= rloI && r0 < rhiI);
                const bool w1 = (r1 >= rloI && r1 < rhiI);
                #pragma unroll
                for (int nt = 0; nt < 4; ++nt) {
                    const int cc = cbase + nt * 8;
                    if (w0) *(float2*)&C[(size_t)r0 * N_DIM + cc] =
                                make_float2(acc[mt][nt][0], acc[mt][nt][1]);
                    if (w1) *(float2*)&C[(size_t)r1 * N_DIM + cc] =
                                make_float2(acc[mt][nt][2], acc[mt][nt][3]);
                }
            }
            #pragma unroll
            for (int i = 0; i < 4; ++i)
                #pragma unroll
                for (int j = 0; j < 4; ++j)
                    #pragma unroll
                    for (int p = 0; p < 4; ++p) acc[i][j][p] = 0.f;
        }
    }
}

extern "C" void kernel_launch(void* const* d_in, const int* in_sizes, int n_in,
                              void* d_out, int out_size)
{
    const float* a = (const float*)d_in[0];    // [M, K]
    const float* b = (const float*)d_in[1];    // [E, N, K]
    const int* seg = nullptr;
    const int* widx = nullptr;
    for (int i = 0; i < n_in; ++i) {
        if (in_sizes[i] == E_SEG + 1)  seg  = (const int*)d_in[i];
        else if (in_sizes[i] == E_SEG) widx = (const int*)d_in[i];
    }
    float* c = (float*)d_out;

    split_AB<<<(NA4 + NB4) / 256, 256>>>((const float4*)a, (const float4*)b);

    cudaFuncSetAttribute(grouped_gemm_hmma,
                         cudaFuncAttributeMaxDynamicSharedMemorySize, SMEM_TOTAL);
    dim3 grid(N_DIM / BN, M_DIM / BM);          // (8, 64) = 512 CTAs
    grouped_gemm_hmma<<<grid, THREADS, SMEM_TOTAL>>>(seg, widx, c);
}

// round 8
// speedup vs baseline: 3.5100x; 1.0920x over previous
#include <cuda_runtime.h>
#include <cuda_fp16.h>
#include <cstdint>

// Grouped GEMM via fp16 2-term split on mma.sync (base sm_103 target).
// C = Ahi@Bh^T + Alo@Bh^T, A = Ahi + Alo (fp16), Bh = fp16(B).
// R8: persistent work-stealing grid (296 CTAs, atomic tile counter),
//     BK=64 2-stage mbarrier cp.async pipeline (half the sync events),
//     2 CTAs/SM.

constexpr int M_DIM = 8192;
constexpr int K_DIM = 1024;
constexpr int N_DIM = 1024;
constexpr int E_SEG = 8;

#define BM 128
#define BN 128
#define BK 64
#define THREADS 256
constexpr int KT = K_DIM / BK;               // 16 k-chunks
constexpr int MAT_BYTES = 128 * 128;         // 16384: 128 rows x 128B (64 fp16)
constexpr int STAGE_BYTES = 3 * MAT_BYTES;   // Ahi, Alo, Bh = 49152
constexpr int NSTAGE = 2;
constexpr int MBAR_OFF = NSTAGE * STAGE_BYTES;   // 98304
constexpr int SMEM_TOTAL = MBAR_OFF + 128;
constexpr int NTILE_X = N_DIM / BN;          // 8
constexpr int NTILES = (M_DIM / BM) * NTILE_X;  // 512
constexpr int GRID_P = 296;                  // 148 SMs x 2 CTAs

// Split storage (fp16)
__device__ __half g_Ahi[(size_t)M_DIM * K_DIM];
__device__ __half g_Alo[(size_t)M_DIM * K_DIM];
__device__ __half g_Bh [(size_t)E_SEG * N_DIM * K_DIM];
__device__ unsigned g_tileCtr;

constexpr int NA4 = (M_DIM * K_DIM) / 4;
constexpr int NB4 = (E_SEG * N_DIM * K_DIM) / 4;

// ---------------- prepass ----------------
__global__ void reset_ctr() { g_tileCtr = 0u; }

__global__ void __launch_bounds__(256)
split_AB(const float4* __restrict__ A, const float4* __restrict__ B) {
    size_t i = (size_t)blockIdx.x * 256 + threadIdx.x;
    if (i < (size_t)NA4) {
        float4 v = A[i];
        __half h0 = __float2half(v.x), h1 = __float2half(v.y);
        __half h2 = __float2half(v.z), h3 = __float2half(v.w);
        __half l0 = __float2half(v.x - __half2float(h0));
        __half l1 = __float2half(v.y - __half2float(h1));
        __half l2 = __float2half(v.z - __half2float(h2));
        __half l3 = __float2half(v.w - __half2float(h3));
        ((ushort4*)g_Ahi)[i] = make_ushort4(__half_as_ushort(h0), __half_as_ushort(h1),
                                            __half_as_ushort(h2), __half_as_ushort(h3));
        ((ushort4*)g_Alo)[i] = make_ushort4(__half_as_ushort(l0), __half_as_ushort(l1),
                                            __half_as_ushort(l2), __half_as_ushort(l3));
    } else {
        size_t j = i - NA4;
        float4 v = B[j];
        ((ushort4*)g_Bh)[j] = make_ushort4(
            __half_as_ushort(__float2half(v.x)), __half_as_ushort(__float2half(v.y)),
            __half_as_ushort(__float2half(v.z)), __half_as_ushort(__float2half(v.w)));
    }
}

// ---------------- asm helpers ----------------
__device__ __forceinline__ void cp16(uint32_t dst, const void* src) {
    asm volatile("cp.async.cg.shared.global [%0], [%1], 16;" :: "r"(dst), "l"(src));
}
__device__ __forceinline__ void ldsm4(uint32_t addr, uint32_t r[4]) {
    asm volatile("ldmatrix.sync.aligned.m8n8.x4.shared.b16 {%0,%1,%2,%3}, [%4];"
                 : "=r"(r[0]), "=r"(r[1]), "=r"(r[2]), "=r"(r[3]) : "r"(addr));
}
__device__ __forceinline__ void mma16816(float d[4], const uint32_t a[4],
                                         uint32_t b0, uint32_t b1) {
    asm volatile(
        "mma.sync.aligned.m16n8k16.row.col.f32.f16.f16.f32 "
        "{%0,%1,%2,%3}, {%4,%5,%6,%7}, {%8,%9}, {%0,%1,%2,%3};"
        : "+f"(d[0]), "+f"(d[1]), "+f"(d[2]), "+f"(d[3])
        : "r"(a[0]), "r"(a[1]), "r"(a[2]), "r"(a[3]), "r"(b0), "r"(b1));
}
__device__ __forceinline__ void mbar_init(uint32_t m, uint32_t cnt) {
    asm volatile("mbarrier.init.shared.b64 [%0], %1;" :: "r"(m), "r"(cnt) : "memory");
}
__device__ __forceinline__ void mbar_arrive(uint32_t m) {
    asm volatile("mbarrier.arrive.shared.b64 _, [%0];" :: "r"(m) : "memory");
}
__device__ __forceinline__ void cpasync_arrive(uint32_t m) {
    asm volatile("cp.async.mbarrier.arrive.noinc.shared.b64 [%0];" :: "r"(m) : "memory");
}
__device__ __forceinline__ void mbar_wait(uint32_t m, uint32_t parity) {
    uint32_t done;
    asm volatile("{\n\t.reg .pred p;\n\t"
                 "mbarrier.try_wait.parity.acquire.cta.shared::cta.b64 p, [%1], %2;\n\t"
                 "selp.b32 %0, 1, 0, p;\n\t}" : "=r"(done) : "r"(m), "r"(parity) : "memory");
    if (!done) {
        asm volatile("{\n\t.reg .pred P1;\n\t"
                     "W_%=:\n\t"
                     "mbarrier.try_wait.parity.acquire.cta.shared::cta.b64 P1, [%0], %1, 0x989680;\n\t"
                     "@P1 bra.uni D_%=;\n\t"
                     "bra.uni W_%=;\n\t"
                     "D_%=:\n\t}" :: "r"(m), "r"(parity) : "memory");
    }
}

// 128B-row SW128 swizzle: XOR chunk bits[6:4] with row bits[2:0].
__device__ __forceinline__ uint32_t swz(uint32_t row, uint32_t colB) {
    return row * 128u + (colB ^ ((row & 7u) << 4));
}

// ---------------- main kernel ----------------
__global__ void __launch_bounds__(THREADS, 2)
grouped_gemm_hmma(const int* __restrict__ seg_indptr,
                  const int* __restrict__ widx,
                  float* __restrict__ C)
{
    extern __shared__ char smem[];
    const uint32_t sb = (uint32_t)__cvta_generic_to_shared(smem);
    const int tid = threadIdx.x;
    const int wid = tid >> 5;
    const int lane = tid & 31;
    const int warp_m = wid >> 2;
    const int warp_n = wid & 3;

    const uint32_t mbF = sb + MBAR_OFF;        // full[i]  at +8*i
    const uint32_t mbE = sb + MBAR_OFF + 16;   // empty[i] at +8*i
    volatile unsigned* sTile = (volatile unsigned*)(smem + MBAR_OFF + 64);

    if (tid == 0) {
        #pragma unroll
        for (int i = 0; i < NSTAGE; ++i) {
            mbar_init(mbF + i * 8, 256);   // one .noinc arrival per thread
            mbar_init(mbE + i * 8, 8);     // one arrival per warp
        }
    }
    __syncthreads();

    // ldmatrix lane addressing
    const uint32_t aRow = (uint32_t)(warp_m * 64 + (lane & 15));
    const uint32_t bRow = (uint32_t)(warp_n * 32 + (lane & 7) + ((lane >> 4) & 1) * 8);
    const uint32_t aSel = (uint32_t)((lane >> 4) * 16);
    const uint32_t bSel = (uint32_t)(((lane >> 3) & 1) * 16);

    // cp.async store mapping: 1024 16B-chunks per matrix, 4 per thread.
    const uint32_t ldR = (uint32_t)(tid >> 3);     // rows 0..31 (+32 per block)
    const uint32_t ldC = (uint32_t)(tid & 7);      // chunk 0..7 in row

    int pst = 0, pph = 1;   // producer cursor
    int cst = 0, cph = 0;   // consumer cursor

    #pragma unroll 1
    for (;;) {
        __syncthreads();                       // prior tile's sTile reads done
        if (tid == 0) *sTile = atomicAdd(&g_tileCtr, 1u);
        __syncthreads();
        const unsigned t = *sTile;
        if (t >= (unsigned)NTILES) break;

        const int row0 = (int)(t >> 3) * BM;
        const int col0 = (int)(t & 7) * BN;

        // enumerate items (segments intersecting this row band)
        int nIt = 0;
        int iRlo[E_SEG], iRhi[E_SEG];
        const __half* iB[E_SEG];
        #pragma unroll 1
        for (int s = 0; s < E_SEG; ++s) {
            const int rlo = max(seg_indptr[s], row0);
            const int rhi = min(seg_indptr[s + 1], row0 + BM);
            if (rlo < rhi) {
                iRlo[nIt] = rlo; iRhi[nIt] = rhi;
                iB[nIt] = g_Bh + (size_t)widx[s] * ((size_t)N_DIM * K_DIM);
                ++nIt;
            }
        }
        const int total = nIt * KT;

        auto produce = [&](int q) {
            const int it = q >> 4;
            const int kt = q & 15;
            mbar_wait(mbE + pst * 8, (uint32_t)pph);
            const uint32_t stg = sb + pst * STAGE_BYTES;
            const int ke = kt * BK + (int)ldC * 8;
            const __half* __restrict__ be = iB[it];
            #pragma unroll
            for (int blk = 0; blk < 4; ++blk) {
                const uint32_t r = ldR + blk * 32;
                const uint32_t so = swz(r, ldC * 16);
                cp16(stg + so,                 g_Ahi + (size_t)(row0 + r) * K_DIM + ke);
                cp16(stg + MAT_BYTES + so,     g_Alo + (size_t)(row0 + r) * K_DIM + ke);
                cp16(stg + 2 * MAT_BYTES + so, be + (size_t)(col0 + r) * K_DIM + ke);
            }
            cpasync_arrive(mbF + pst * 8);
            if (++pst == NSTAGE) { pst = 0; pph ^= 1; }
        };

        float acc[4][4][4];
        #pragma unroll
        for (int i = 0; i < 4; ++i)
            #pragma unroll
            for (int j = 0; j < 4; ++j)
                #pragma unroll
                for (int p = 0; p < 4; ++p) acc[i][j][p] = 0.f;

        produce(0);

        #pragma unroll 1
        for (int q = 0; q < total; ++q) {
            if (q + 1 < total) produce(q + 1);   // issue copies before waiting
            mbar_wait(mbF + cst * 8, (uint32_t)cph);

            const uint32_t stg    = sb + cst * STAGE_BYTES;
            const uint32_t stgAhi = stg;
            const uint32_t stgAlo = stg + MAT_BYTES;
            const uint32_t stgBh  = stg + 2 * MAT_BYTES;

            #pragma unroll
            for (int kh = 0; kh < 4; ++kh) {
                const uint32_t aCB = (uint32_t)(kh * 32) + aSel;
                const uint32_t bCB = (uint32_t)(kh * 32) + bSel;

                uint32_t ah[4][4], bh[2][4];
                #pragma unroll
                for (int mt = 0; mt < 4; ++mt)
                    ldsm4(stgAhi + swz(aRow + mt * 16, aCB), ah[mt]);
                #pragma unroll
                for (int p = 0; p < 2; ++p)
                    ldsm4(stgBh + swz(bRow + p * 16, bCB), bh[p]);

                #pragma unroll
                for (int mt = 0; mt < 4; ++mt)
                    #pragma unroll
                    for (int nt = 0; nt < 4; ++nt)
                        mma16816(acc[mt][nt], ah[mt],
                                 bh[nt >> 1][(nt & 1) * 2], bh[nt >> 1][(nt & 1) * 2 + 1]);

                uint32_t al[4][4];
                #pragma unroll
                for (int mt = 0; mt < 4; ++mt)
                    ldsm4(stgAlo + swz(aRow + mt * 16, aCB), al[mt]);

                #pragma unroll
                for (int mt = 0; mt < 4; ++mt)
                    #pragma unroll
                    for (int nt = 0; nt < 4; ++nt)
                        mma16816(acc[mt][nt], al[mt],
                                 bh[nt >> 1][(nt & 1) * 2], bh[nt >> 1][(nt & 1) * 2 + 1]);
            }

            if (lane == 0) mbar_arrive(mbE + cst * 8);
            if (++cst == NSTAGE) { cst = 0; cph ^= 1; }

            // item boundary -> epilogue + acc reset
            if ((q & 15) == 15) {
                const int it = q >> 4;
                const int rloI = iRlo[it], rhiI = iRhi[it];
                const int cbase = col0 + warp_n * 32 + (lane & 3) * 2;
                #pragma unroll
                for (int mt = 0; mt < 4; ++mt) {
                    const int r0 = row0 + warp_m * 64 + mt * 16 + (lane >> 2);
                    const int r1 = r0 + 8;
                    const bool w0 = (r0 >= rloI && r0 < rhiI);
                    const bool w1 = (r1 >= rloI && r1 < rhiI);
                    #pragma unroll
                    for (int nt = 0; nt < 4; ++nt) {
                        const int cc = cbase + nt * 8;
                        if (w0) *(float2*)&C[(size_t)r0 * N_DIM + cc] =
                                    make_float2(acc[mt][nt][0], acc[mt][nt][1]);
                        if (w1) *(float2*)&C[(size_t)r1 * N_DIM + cc] =
                                    make_float2(acc[mt][nt][2], acc[mt][nt][3]);
                    }
                }
                #pragma unroll
                for (int i = 0; i < 4; ++i)
                    #pragma unroll
                    for (int j = 0; j < 4; ++j)
                        #pragma unroll
                        for (int p = 0; p < 4; ++p) acc[i][j][p] = 0.f;
            }
        }
    }
}

extern "C" void kernel_launch(void* const* d_in, const int* in_sizes, int n_in,
                              void* d_out, int out_size)
{
    const float* a = (const float*)d_in[0];    // [M, K]
    const float* b = (const float*)d_in[1];    // [E, N, K]
    const int* seg = nullptr;
    const int* widx = nullptr;
    for (int i = 0; i < n_in; ++i) {
        if (in_sizes[i] == E_SEG + 1)  seg  = (const int*)d_in[i];
        else if (in_sizes[i] == E_SEG) widx = (const int*)d_in[i];
    }
    float* c = (float*)d_out;

    reset_ctr<<<1, 1>>>();
    split_AB<<<(NA4 + NB4) / 256, 256>>>((const float4*)a, (const float4*)b);

    cudaFuncSetAttribute(grouped_gemm_hmma,
                         cudaFuncAttributeMaxDynamicSharedMemorySize, SMEM_TOTAL);
    grouped_gemm_hmma<<<GRID_P, THREADS, SMEM_TOTAL>>>(seg, widx, c);
}